// round 10
// baseline (speedup 1.0000x reference)
#include <cuda_runtime.h>
#include <cuda_fp16.h>
#include <cstdint>

#define D 128
#define NMAX 100000
#define EMAX 3200000
#define FULL 0xffffffffu

// Scratch in device globals (no runtime allocation).
__device__ float  g_h0[NMAX * D];
__device__ __half g_h1h[NMAX * D];      // h1 in fp16 (agg gather payload)
__device__ float  g_aself[NMAX];
__device__ float  g_aneigh[NMAX];
__device__ int    g_deg[NMAX + 4];      // padded for int4 scan reads
__device__ int    g_off[NMAX + 1];
__device__ int    g_cur[NMAX];
__device__ int2   g_epack[EMAX];        // {col, f32 bits of a_neigh[col]}

// ---------------------------------------------------------------------------
// Tensor-core GEMM (tf32 mma.sync m16n8k8), 64-row tiles for 2 CTAs/SM.
// Grid (ceil(N/64), 2): cb=0 -> h0 (fp32) + a_self; cb=1 -> h1 (fp16) + a_neigh.
// CTA: 256 thr (8 warps: 4 along M x 2 along N), tile 64 rows x 128 cols.
// smem ~100.3 KB -> 2 CTAs/SM (16 warps) vs previous 137 KB (1 CTA).
// ---------------------------------------------------------------------------
#define TSTRIDE 132
#define XS_WORDS (64 * TSTRIDE)
#define WS_WORDS (128 * TSTRIDE)
#define GEMM_SMEM ((XS_WORDS + WS_WORDS + 64 + 2 * 128) * 4)

__device__ __forceinline__ uint32_t f2tf32(float f)
{
    uint32_t u;
    asm("cvt.rna.tf32.f32 %0, %1;" : "=r"(u) : "f"(f));
    return u;
}

__device__ __forceinline__ void mma_tf32(float* c, const uint32_t* a,
                                         uint32_t b0, uint32_t b1)
{
    asm volatile(
        "mma.sync.aligned.m16n8k8.row.col.f32.tf32.tf32.f32 "
        "{%0,%1,%2,%3}, {%4,%5,%6,%7}, {%8,%9}, {%0,%1,%2,%3};"
        : "+f"(c[0]), "+f"(c[1]), "+f"(c[2]), "+f"(c[3])
        : "r"(a[0]), "r"(a[1]), "r"(a[2]), "r"(a[3]), "r"(b0), "r"(b1));
}

__global__ __launch_bounds__(256, 2) void gemm_kernel(
    const float* __restrict__ x,
    const float* __restrict__ W0, const float* __restrict__ b0,
    const float* __restrict__ W1, const float* __restrict__ b1,
    const float* __restrict__ att, int N)
{
    extern __shared__ uint32_t sm[];
    uint32_t* xs = sm;                    // [64][TSTRIDE] tf32 bits
    uint32_t* ws = sm + XS_WORDS;         // [128][TSTRIDE] tf32 bits
    float* rowsum = (float*)(sm + XS_WORDS + WS_WORDS);   // [64]
    float* sbias  = rowsum + 64;                          // [128]
    float* satt   = sbias + 128;                          // [128]

    const int tid  = threadIdx.x;
    const int row0 = blockIdx.x * 64;
    const int cb   = blockIdx.y;
    const float* W  = cb ? W1 : W0;
    const float* bv = cb ? b1 : b0;

    if (tid < 128) {
        sbias[tid] = bv[tid];
        satt[tid]  = att[cb * 128 + tid];
    }
    if (tid < 64) {
        rowsum[tid] = 0.0f;
        if (cb == 0 && row0 + tid < N) g_deg[row0 + tid] = 0;
    }

    // Stage W (128x128) and x tile (64x128) as tf32 bits.
    for (int i = tid; i < 128 * 128; i += 256) {
        int r = i >> 7, c = i & 127;
        ws[r * TSTRIDE + c] = f2tf32(W[r * 128 + c]);
    }
    for (int i = tid; i < 64 * 128; i += 256) {
        int r = i >> 7, c = i & 127;
        int gr = row0 + r;
        float xv = (gr < N) ? x[(size_t)gr * 128 + c] : 0.0f;
        xs[r * TSTRIDE + c] = f2tf32(xv);
    }
    __syncthreads();

    const int lane = tid & 31, wid = tid >> 5;
    const int gid  = lane >> 2, tg = lane & 3;
    const int mrow = (wid >> 1) * 16;   // 0,16,32,48
    const int ncol = (wid & 1) * 64;    // 0,64

    float acc[8][4];
#pragma unroll
    for (int nt = 0; nt < 8; nt++)
#pragma unroll
        for (int q = 0; q < 4; q++) acc[nt][q] = 0.0f;

#pragma unroll 4
    for (int ks = 0; ks < 16; ks++) {
        const int k0 = ks * 8;
        uint32_t a[4];
        {
            int r = mrow + gid;
            a[0] = xs[(r    ) * TSTRIDE + k0 + tg    ];
            a[1] = xs[(r + 8) * TSTRIDE + k0 + tg    ];
            a[2] = xs[(r    ) * TSTRIDE + k0 + tg + 4];
            a[3] = xs[(r + 8) * TSTRIDE + k0 + tg + 4];
        }
#pragma unroll
        for (int nt = 0; nt < 8; nt++) {
            int n = ncol + nt * 8 + gid;
            uint32_t bq0 = ws[n * TSTRIDE + k0 + tg    ];
            uint32_t bq1 = ws[n * TSTRIDE + k0 + tg + 4];
            mma_tf32(acc[nt], a, bq0, bq1);
        }
    }

    // Epilogue: bias + relu, store h (fp32 h0 / fp16 h1), attention dot per row.
    float pr0 = 0.0f, pr1 = 0.0f;
    const int rbase = row0 + mrow;
#pragma unroll
    for (int nt = 0; nt < 8; nt++) {
        int n = ncol + nt * 8 + 2 * tg;
        float bia0 = sbias[n], bia1 = sbias[n + 1];
        float at0  = satt[n],  at1  = satt[n + 1];
        float v00 = fmaxf(acc[nt][0] + bia0, 0.0f);
        float v01 = fmaxf(acc[nt][1] + bia1, 0.0f);
        float v10 = fmaxf(acc[nt][2] + bia0, 0.0f);
        float v11 = fmaxf(acc[nt][3] + bia1, 0.0f);
        int r0r = rbase + gid, r1r = rbase + gid + 8;
        if (cb == 0) {
            if (r0r < N) *(float2*)(g_h0 + (size_t)r0r * 128 + n) = make_float2(v00, v01);
            if (r1r < N) *(float2*)(g_h0 + (size_t)r1r * 128 + n) = make_float2(v10, v11);
        } else {
            if (r0r < N) *(__half2*)(g_h1h + (size_t)r0r * 128 + n) =
                __floats2half2_rn(v00, v01);
            if (r1r < N) *(__half2*)(g_h1h + (size_t)r1r * 128 + n) =
                __floats2half2_rn(v10, v11);
        }
        pr0 += v00 * at0 + v01 * at1;
        pr1 += v10 * at0 + v11 * at1;
    }
    // Reduce over the quad (tg), then combine the 2 N-warps via smem atomics.
    pr0 += __shfl_xor_sync(FULL, pr0, 1);
    pr0 += __shfl_xor_sync(FULL, pr0, 2);
    pr1 += __shfl_xor_sync(FULL, pr1, 1);
    pr1 += __shfl_xor_sync(FULL, pr1, 2);
    if (tg == 0) {
        atomicAdd(&rowsum[mrow + gid    ], pr0);
        atomicAdd(&rowsum[mrow + gid + 8], pr1);
    }
    __syncthreads();
    if (tid < 64) {
        int gr = row0 + tid;
        if (gr < N) {
            float p = rowsum[tid];
            p = (p > 0.0f) ? p : 0.2f * p;
            if (cb) g_aneigh[gr] = p;
            else    g_aself[gr]  = p;
        }
    }
}

// ---------------------------------------------------------------------------
// CSR build: histogram -> single-block scan -> cursor scatter (packs e-values)
// ---------------------------------------------------------------------------
__global__ __launch_bounds__(256) void hist_kernel(const int* __restrict__ row, int E)
{
    int i = blockIdx.x * 256 + threadIdx.x;
    if (i < E) atomicAdd(&g_deg[row[i]], 1);
}

// Single-block exclusive scan of g_deg[0..N): g_cur[i] = exclusive prefix,
// g_off[i+1] = inclusive. 1024 threads, 100-element chunks (int4 loads).
#define SCAN_CHUNK 100
__global__ __launch_bounds__(1024) void scan_kernel(int N)
{
    __shared__ int wsum[32];
    const int t = threadIdx.x;
    const int base = t * SCAN_CHUNK;

    int sum = 0;
#pragma unroll
    for (int u = 0; u < SCAN_CHUNK / 4; u++) {
        int idx = base + u * 4;
        if (idx < N) {
            int4 v = *(const int4*)(g_deg + idx);   // g_deg padded by 4
            sum += v.x;
            if (idx + 1 < N) sum += v.y;
            if (idx + 2 < N) sum += v.z;
            if (idx + 3 < N) sum += v.w;
        }
    }

    const int lane = t & 31, w = t >> 5;
    int v = sum;
#pragma unroll
    for (int o = 1; o < 32; o <<= 1) {
        int n = __shfl_up_sync(FULL, v, o);
        if (lane >= o) v += n;
    }
    if (lane == 31) wsum[w] = v;
    __syncthreads();
    if (w == 0) {
        int s = wsum[lane];
#pragma unroll
        for (int o = 1; o < 32; o <<= 1) {
            int n = __shfl_up_sync(FULL, s, o);
            if (lane >= o) s += n;
        }
        wsum[lane] = s;
    }
    __syncthreads();
    int excl = v - sum + (w > 0 ? wsum[w - 1] : 0);

    int running = excl;
#pragma unroll
    for (int u = 0; u < SCAN_CHUNK / 4; u++) {
        int idx = base + u * 4;
        if (idx < N) {
            int4 dv = *(const int4*)(g_deg + idx);
            int d[4] = {dv.x, dv.y, dv.z, dv.w};
#pragma unroll
            for (int q = 0; q < 4; q++) {
                if (idx + q < N) {
                    g_cur[idx + q] = running;
                    running += d[q];
                    g_off[idx + q + 1] = running;
                }
            }
        }
    }
    if (t == 0) g_off[0] = 0;
}

__global__ __launch_bounds__(256) void scatter_kernel(
    const int* __restrict__ row, const int* __restrict__ col, int E)
{
    int i = blockIdx.x * 256 + threadIdx.x;
    if (i < E) {
        int c = col[i];
        int pos = atomicAdd(&g_cur[row[i]], 1);
        g_epack[pos] = make_int2(c, __float_as_int(g_aneigh[c]));
    }
}

// ---------------------------------------------------------------------------
// Aggregate + fused epilogue: one warp per node (gather, no atomics).
//   agg = sum_{(r,c)} (a_self[r]+a_neigh[c]) * h1[c]   (h1 fp16, e pre-packed)
//   out[r] = norm(h0[r],s0,o0) + norm(agg,s1,o1)
// ---------------------------------------------------------------------------
__global__ __launch_bounds__(256) void agg_kernel(
    const float* __restrict__ scale0, const float* __restrict__ offset0,
    const float* __restrict__ scale1, const float* __restrict__ offset1,
    float* __restrict__ out, int N)
{
    int gw = (blockIdx.x * blockDim.x + threadIdx.x) >> 5;
    int lane = threadIdx.x & 31;
    if (gw >= N) return;

    const int start = g_off[gw];
    const int end   = g_off[gw + 1];
    const float a_r = g_aself[gw];

    float4 acc = make_float4(0.f, 0.f, 0.f, 0.f);

    for (int base = start; base < end; base += 32) {
        int idx = base + lane;
        int2 p = (idx < end) ? g_epack[idx] : make_int2(0, 0);
        int   c = p.x;
        float e = a_r + __int_as_float(p.y);
        int cnt = min(32, end - base);
        int j = 0;
        for (; j + 4 <= cnt; j += 4) {
#pragma unroll
            for (int u = 0; u < 4; u++) {
                int   cj = __shfl_sync(FULL, c, j + u);
                float ej = __shfl_sync(FULL, e, j + u);
                uint2 hp = ((const uint2*)(g_h1h + (size_t)cj * 128))[lane];
                float2 lo = __half22float2(*(__half2*)&hp.x);
                float2 hi = __half22float2(*(__half2*)&hp.y);
                acc.x = fmaf(ej, lo.x, acc.x);
                acc.y = fmaf(ej, lo.y, acc.y);
                acc.z = fmaf(ej, hi.x, acc.z);
                acc.w = fmaf(ej, hi.y, acc.w);
            }
        }
        for (; j < cnt; j++) {
            int   cj = __shfl_sync(FULL, c, j);
            float ej = __shfl_sync(FULL, e, j);
            uint2 hp = ((const uint2*)(g_h1h + (size_t)cj * 128))[lane];
            float2 lo = __half22float2(*(__half2*)&hp.x);
            float2 hi = __half22float2(*(__half2*)&hp.y);
            acc.x = fmaf(ej, lo.x, acc.x);
            acc.y = fmaf(ej, lo.y, acc.y);
            acc.z = fmaf(ej, hi.x, acc.z);
            acc.w = fmaf(ej, hi.y, acc.w);
        }
    }

    const float4 h0v = ((const float4*)(g_h0 + (size_t)gw * 128))[lane];

    float s0 = h0v.x + h0v.y + h0v.z + h0v.w;
    float q0 = h0v.x * h0v.x + h0v.y * h0v.y + h0v.z * h0v.z + h0v.w * h0v.w;
    float s1 = acc.x + acc.y + acc.z + acc.w;
    float q1 = acc.x * acc.x + acc.y * acc.y + acc.z * acc.z + acc.w * acc.w;

#pragma unroll
    for (int o = 16; o > 0; o >>= 1) {
        s0 += __shfl_xor_sync(FULL, s0, o);
        q0 += __shfl_xor_sync(FULL, q0, o);
        s1 += __shfl_xor_sync(FULL, s1, o);
        q1 += __shfl_xor_sync(FULL, q1, o);
    }

    const float m0 = s0 * (1.0f / 128.0f);
    const float i0 = rsqrtf(q0 * (1.0f / 128.0f) - m0 * m0 + 1e-9f);
    const float m1 = s1 * (1.0f / 128.0f);
    const float i1 = rsqrtf(q1 * (1.0f / 128.0f) - m1 * m1 + 1e-9f);

    const float4 sc0 = ((const float4*)scale0)[lane];
    const float4 of0 = ((const float4*)offset0)[lane];
    const float4 sc1 = ((const float4*)scale1)[lane];
    const float4 of1 = ((const float4*)offset1)[lane];

    float4 o4;
    o4.x = (h0v.x - m0) * sc0.x * i0 + of0.x + (acc.x - m1) * sc1.x * i1 + of1.x;
    o4.y = (h0v.y - m0) * sc0.y * i0 + of0.y + (acc.y - m1) * sc1.y * i1 + of1.y;
    o4.z = (h0v.z - m0) * sc0.z * i0 + of0.z + (acc.z - m1) * sc1.z * i1 + of1.z;
    o4.w = (h0v.w - m0) * sc0.w * i0 + of0.w + (acc.w - m1) * sc1.w * i1 + of1.w;
    ((float4*)(out + (size_t)gw * 128))[lane] = o4;
}

// ---------------------------------------------------------------------------
extern "C" void kernel_launch(void* const* d_in, const int* in_sizes, int n_in,
                              void* d_out, int out_size)
{
    const float* x       = (const float*)d_in[0];
    const int*   row     = (const int*)  d_in[1];
    const int*   col     = (const int*)  d_in[2];
    const float* W0      = (const float*)d_in[3];
    const float* b0      = (const float*)d_in[4];
    const float* W1      = (const float*)d_in[5];
    const float* b1      = (const float*)d_in[6];
    const float* att     = (const float*)d_in[7];
    const float* scale0  = (const float*)d_in[8];
    const float* offset0 = (const float*)d_in[9];
    const float* scale1  = (const float*)d_in[10];
    const float* offset1 = (const float*)d_in[11];
    float* out = (float*)d_out;

    const int N = in_sizes[0] / D;
    const int E = in_sizes[1];

    cudaFuncSetAttribute(gemm_kernel, cudaFuncAttributeMaxDynamicSharedMemorySize,
                         GEMM_SMEM);

    dim3 ggrid((N + 63) / 64, 2);
    gemm_kernel<<<ggrid, 256, GEMM_SMEM>>>(x, W0, b0, W1, b1, att, N);
    hist_kernel<<<(E + 255) / 256, 256>>>(row, E);
    scan_kernel<<<1, 1024>>>(N);
    scatter_kernel<<<(E + 255) / 256, 256>>>(row, col, E);
    agg_kernel<<<(N * 32 + 255) / 256, 256>>>(scale0, offset0, scale1, offset1, out, N);
}

// round 11
// speedup vs baseline: 1.2019x; 1.2019x over previous
#include <cuda_runtime.h>
#include <cuda_fp16.h>
#include <cstdint>

#define D 128
#define NMAX 100000
#define EMAX 3200000
#define FULL 0xffffffffu

// Scratch in device globals (no runtime allocation).
__device__ float  g_h0[NMAX * D];
__device__ __half g_h1h[NMAX * D];      // h1 in fp16 (agg gather payload)
__device__ float  g_aself[NMAX];
__device__ float  g_aneigh[NMAX];
__device__ int    g_deg[NMAX + 4];      // padded for int4 scan reads
__device__ int    g_off[NMAX + 1];
__device__ int    g_cur[NMAX];
__device__ int2   g_epack[EMAX];        // {col, f32 bits of a_neigh[col]}

// ---------------------------------------------------------------------------
// Tensor-core GEMM, fp16 mma.sync m16n8k16 (fp32 accumulate).
// Grid (ceil(N/128), 2): cb=0 -> h0 (fp32) + a_self; cb=1 -> h1 (fp16) + a_neigh.
// CTA: 256 thr (8 warps: 4 along M x 2 along N), tile 128 rows x 128 cols.
// smem: x + W tiles in half, stride 136 -> 71.2 KB -> 2 CTAs/SM.
// fp16 has the same 10 mantissa bits as tf32 -> precision unchanged.
// ---------------------------------------------------------------------------
#define HSTRIDE 136
#define TILE_HALVES (128 * HSTRIDE)
#define GEMM_SMEM (2 * TILE_HALVES * 2 + 3 * 128 * 4)

__device__ __forceinline__ void mma_f16(float* c, const uint32_t* a,
                                        uint32_t b0, uint32_t b1)
{
    asm volatile(
        "mma.sync.aligned.m16n8k16.row.col.f32.f16.f16.f32 "
        "{%0,%1,%2,%3}, {%4,%5,%6,%7}, {%8,%9}, {%0,%1,%2,%3};"
        : "+f"(c[0]), "+f"(c[1]), "+f"(c[2]), "+f"(c[3])
        : "r"(a[0]), "r"(a[1]), "r"(a[2]), "r"(a[3]), "r"(b0), "r"(b1));
}

__global__ __launch_bounds__(256, 2) void gemm_kernel(
    const float* __restrict__ x,
    const float* __restrict__ W0, const float* __restrict__ b0,
    const float* __restrict__ W1, const float* __restrict__ b1,
    const float* __restrict__ att, int N)
{
    extern __shared__ __half smh[];
    __half* xs = smh;                     // [128][HSTRIDE]
    __half* ws = smh + TILE_HALVES;       // [128][HSTRIDE]
    float* rowsum = (float*)(smh + 2 * TILE_HALVES);  // [128]
    float* sbias  = rowsum + 128;                     // [128]
    float* satt   = sbias + 128;                      // [128]

    const int tid  = threadIdx.x;
    const int row0 = blockIdx.x * 128;
    const int cb   = blockIdx.y;
    const float* W  = cb ? W1 : W0;
    const float* bv = cb ? b1 : b0;

    if (tid < 128) {
        rowsum[tid] = 0.0f;
        sbias[tid]  = bv[tid];
        satt[tid]   = att[cb * 128 + tid];
        if (cb == 0 && row0 + tid < N) g_deg[row0 + tid] = 0;
    }

    // Stage W and x tiles as fp16 (float2 -> half2, halves the store count).
    for (int i = tid; i < 128 * 64; i += 256) {
        int r = i >> 6, c2 = (i & 63) * 2;
        float2 wv = *(const float2*)(W + r * 128 + c2);
        *(__half2*)(ws + r * HSTRIDE + c2) = __floats2half2_rn(wv.x, wv.y);
        int gr = row0 + r;
        float2 xv = (gr < N) ? *(const float2*)(x + (size_t)gr * 128 + c2)
                             : make_float2(0.0f, 0.0f);
        *(__half2*)(xs + r * HSTRIDE + c2) = __floats2half2_rn(xv.x, xv.y);
    }
    __syncthreads();

    const int lane = tid & 31, wid = tid >> 5;
    const int gid  = lane >> 2, tg = lane & 3;
    const int mrow = (wid >> 1) * 32;   // 0,32,64,96
    const int ncol = (wid & 1) * 64;    // 0,64

    float acc[2][8][4];
#pragma unroll
    for (int mt = 0; mt < 2; mt++)
#pragma unroll
        for (int nt = 0; nt < 8; nt++)
#pragma unroll
            for (int q = 0; q < 4; q++) acc[mt][nt][q] = 0.0f;

#pragma unroll
    for (int ks = 0; ks < 8; ks++) {
        const int k0 = ks * 16;
        uint32_t a[2][4];
#pragma unroll
        for (int mt = 0; mt < 2; mt++) {
            int r = mrow + mt * 16 + gid;
            a[mt][0] = *(const uint32_t*)(xs + (r    ) * HSTRIDE + k0     + tg * 2);
            a[mt][1] = *(const uint32_t*)(xs + (r + 8) * HSTRIDE + k0     + tg * 2);
            a[mt][2] = *(const uint32_t*)(xs + (r    ) * HSTRIDE + k0 + 8 + tg * 2);
            a[mt][3] = *(const uint32_t*)(xs + (r + 8) * HSTRIDE + k0 + 8 + tg * 2);
        }
#pragma unroll
        for (int nt = 0; nt < 8; nt++) {
            int n = ncol + nt * 8 + gid;
            uint32_t bq0 = *(const uint32_t*)(ws + n * HSTRIDE + k0     + tg * 2);
            uint32_t bq1 = *(const uint32_t*)(ws + n * HSTRIDE + k0 + 8 + tg * 2);
#pragma unroll
            for (int mt = 0; mt < 2; mt++)
                mma_f16(acc[mt][nt], a[mt], bq0, bq1);
        }
    }

    // Epilogue: bias + relu, store h (fp32 h0 / fp16 h1), attention dot per row.
    float pr[2][2] = {{0.f, 0.f}, {0.f, 0.f}};
#pragma unroll
    for (int mt = 0; mt < 2; mt++) {
        int rbase = row0 + mrow + mt * 16;
#pragma unroll
        for (int nt = 0; nt < 8; nt++) {
            int n = ncol + nt * 8 + 2 * tg;
            float bia0 = sbias[n], bia1 = sbias[n + 1];
            float at0  = satt[n],  at1  = satt[n + 1];
            float v00 = fmaxf(acc[mt][nt][0] + bia0, 0.0f);
            float v01 = fmaxf(acc[mt][nt][1] + bia1, 0.0f);
            float v10 = fmaxf(acc[mt][nt][2] + bia0, 0.0f);
            float v11 = fmaxf(acc[mt][nt][3] + bia1, 0.0f);
            int r0r = rbase + gid, r1r = rbase + gid + 8;
            if (cb == 0) {
                if (r0r < N) *(float2*)(g_h0 + (size_t)r0r * 128 + n) = make_float2(v00, v01);
                if (r1r < N) *(float2*)(g_h0 + (size_t)r1r * 128 + n) = make_float2(v10, v11);
            } else {
                if (r0r < N) *(__half2*)(g_h1h + (size_t)r0r * 128 + n) =
                    __floats2half2_rn(v00, v01);
                if (r1r < N) *(__half2*)(g_h1h + (size_t)r1r * 128 + n) =
                    __floats2half2_rn(v10, v11);
            }
            pr[mt][0] += v00 * at0 + v01 * at1;
            pr[mt][1] += v10 * at0 + v11 * at1;
        }
    }
#pragma unroll
    for (int mt = 0; mt < 2; mt++)
#pragma unroll
        for (int h = 0; h < 2; h++) {
            float p = pr[mt][h];
            p += __shfl_xor_sync(FULL, p, 1);
            p += __shfl_xor_sync(FULL, p, 2);
            pr[mt][h] = p;
        }
    if (tg == 0) {
        atomicAdd(&rowsum[mrow + gid     ], pr[0][0]);
        atomicAdd(&rowsum[mrow + gid + 8 ], pr[0][1]);
        atomicAdd(&rowsum[mrow + gid + 16], pr[1][0]);
        atomicAdd(&rowsum[mrow + gid + 24], pr[1][1]);
    }
    __syncthreads();
    if (tid < 128) {
        int gr = row0 + tid;
        if (gr < N) {
            float p = rowsum[tid];
            p = (p > 0.0f) ? p : 0.2f * p;
            if (cb) g_aneigh[gr] = p;
            else    g_aself[gr]  = p;
        }
    }
}

// ---------------------------------------------------------------------------
// CSR build: histogram -> single-block scan -> cursor scatter (packs e-values)
// ---------------------------------------------------------------------------
__global__ __launch_bounds__(256) void hist_kernel(const int* __restrict__ row, int E)
{
    int i = blockIdx.x * 256 + threadIdx.x;
    if (i < E) atomicAdd(&g_deg[row[i]], 1);
}

// Single-block exclusive scan of g_deg[0..N): g_cur[i] = exclusive prefix,
// g_off[i+1] = inclusive. 1024 threads, 100-element chunks (int4 loads).
#define SCAN_CHUNK 100
__global__ __launch_bounds__(1024) void scan_kernel(int N)
{
    __shared__ int wsum[32];
    const int t = threadIdx.x;
    const int base = t * SCAN_CHUNK;

    int sum = 0;
#pragma unroll
    for (int u = 0; u < SCAN_CHUNK / 4; u++) {
        int idx = base + u * 4;
        if (idx < N) {
            int4 v = *(const int4*)(g_deg + idx);   // g_deg padded by 4
            sum += v.x;
            if (idx + 1 < N) sum += v.y;
            if (idx + 2 < N) sum += v.z;
            if (idx + 3 < N) sum += v.w;
        }
    }

    const int lane = t & 31, w = t >> 5;
    int v = sum;
#pragma unroll
    for (int o = 1; o < 32; o <<= 1) {
        int n = __shfl_up_sync(FULL, v, o);
        if (lane >= o) v += n;
    }
    if (lane == 31) wsum[w] = v;
    __syncthreads();
    if (w == 0) {
        int s = wsum[lane];
#pragma unroll
        for (int o = 1; o < 32; o <<= 1) {
            int n = __shfl_up_sync(FULL, s, o);
            if (lane >= o) s += n;
        }
        wsum[lane] = s;
    }
    __syncthreads();
    int excl = v - sum + (w > 0 ? wsum[w - 1] : 0);

    int running = excl;
#pragma unroll
    for (int u = 0; u < SCAN_CHUNK / 4; u++) {
        int idx = base + u * 4;
        if (idx < N) {
            int4 dv = *(const int4*)(g_deg + idx);
            int d[4] = {dv.x, dv.y, dv.z, dv.w};
#pragma unroll
            for (int q = 0; q < 4; q++) {
                if (idx + q < N) {
                    g_cur[idx + q] = running;
                    running += d[q];
                    g_off[idx + q + 1] = running;
                }
            }
        }
    }
    if (t == 0) g_off[0] = 0;
}

__global__ __launch_bounds__(256) void scatter_kernel(
    const int* __restrict__ row, const int* __restrict__ col, int E)
{
    int i = blockIdx.x * 256 + threadIdx.x;
    if (i < E) {
        int c = col[i];
        int pos = atomicAdd(&g_cur[row[i]], 1);
        g_epack[pos] = make_int2(c, __float_as_int(g_aneigh[c]));
    }
}

// ---------------------------------------------------------------------------
// Aggregate + fused epilogue: one warp per node (gather, no atomics).
//   agg = sum_{(r,c)} (a_self[r]+a_neigh[c]) * h1[c]   (h1 fp16, e pre-packed)
//   out[r] = norm(h0[r],s0,o0) + norm(agg,s1,o1)
// ---------------------------------------------------------------------------
__global__ __launch_bounds__(256) void agg_kernel(
    const float* __restrict__ scale0, const float* __restrict__ offset0,
    const float* __restrict__ scale1, const float* __restrict__ offset1,
    float* __restrict__ out, int N)
{
    int gw = (blockIdx.x * blockDim.x + threadIdx.x) >> 5;
    int lane = threadIdx.x & 31;
    if (gw >= N) return;

    const int start = g_off[gw];
    const int end   = g_off[gw + 1];
    const float a_r = g_aself[gw];

    float4 acc = make_float4(0.f, 0.f, 0.f, 0.f);

    for (int base = start; base < end; base += 32) {
        int idx = base + lane;
        int2 p = (idx < end) ? g_epack[idx] : make_int2(0, 0);
        int   c = p.x;
        float e = a_r + __int_as_float(p.y);
        int cnt = min(32, end - base);
        int j = 0;
        for (; j + 4 <= cnt; j += 4) {
#pragma unroll
            for (int u = 0; u < 4; u++) {
                int   cj = __shfl_sync(FULL, c, j + u);
                float ej = __shfl_sync(FULL, e, j + u);
                uint2 hp = ((const uint2*)(g_h1h + (size_t)cj * 128))[lane];
                float2 lo = __half22float2(*(__half2*)&hp.x);
                float2 hi = __half22float2(*(__half2*)&hp.y);
                acc.x = fmaf(ej, lo.x, acc.x);
                acc.y = fmaf(ej, lo.y, acc.y);
                acc.z = fmaf(ej, hi.x, acc.z);
                acc.w = fmaf(ej, hi.y, acc.w);
            }
        }
        for (; j < cnt; j++) {
            int   cj = __shfl_sync(FULL, c, j);
            float ej = __shfl_sync(FULL, e, j);
            uint2 hp = ((const uint2*)(g_h1h + (size_t)cj * 128))[lane];
            float2 lo = __half22float2(*(__half2*)&hp.x);
            float2 hi = __half22float2(*(__half2*)&hp.y);
            acc.x = fmaf(ej, lo.x, acc.x);
            acc.y = fmaf(ej, lo.y, acc.y);
            acc.z = fmaf(ej, hi.x, acc.z);
            acc.w = fmaf(ej, hi.y, acc.w);
        }
    }

    const float4 h0v = ((const float4*)(g_h0 + (size_t)gw * 128))[lane];

    float s0 = h0v.x + h0v.y + h0v.z + h0v.w;
    float q0 = h0v.x * h0v.x + h0v.y * h0v.y + h0v.z * h0v.z + h0v.w * h0v.w;
    float s1 = acc.x + acc.y + acc.z + acc.w;
    float q1 = acc.x * acc.x + acc.y * acc.y + acc.z * acc.z + acc.w * acc.w;

#pragma unroll
    for (int o = 16; o > 0; o >>= 1) {
        s0 += __shfl_xor_sync(FULL, s0, o);
        q0 += __shfl_xor_sync(FULL, q0, o);
        s1 += __shfl_xor_sync(FULL, s1, o);
        q1 += __shfl_xor_sync(FULL, q1, o);
    }

    const float m0 = s0 * (1.0f / 128.0f);
    const float i0 = rsqrtf(q0 * (1.0f / 128.0f) - m0 * m0 + 1e-9f);
    const float m1 = s1 * (1.0f / 128.0f);
    const float i1 = rsqrtf(q1 * (1.0f / 128.0f) - m1 * m1 + 1e-9f);

    const float4 sc0 = ((const float4*)scale0)[lane];
    const float4 of0 = ((const float4*)offset0)[lane];
    const float4 sc1 = ((const float4*)scale1)[lane];
    const float4 of1 = ((const float4*)offset1)[lane];

    float4 o4;
    o4.x = (h0v.x - m0) * sc0.x * i0 + of0.x + (acc.x - m1) * sc1.x * i1 + of1.x;
    o4.y = (h0v.y - m0) * sc0.y * i0 + of0.y + (acc.y - m1) * sc1.y * i1 + of1.y;
    o4.z = (h0v.z - m0) * sc0.z * i0 + of0.z + (acc.z - m1) * sc1.z * i1 + of1.z;
    o4.w = (h0v.w - m0) * sc0.w * i0 + of0.w + (acc.w - m1) * sc1.w * i1 + of1.w;
    ((float4*)(out + (size_t)gw * 128))[lane] = o4;
}

// ---------------------------------------------------------------------------
extern "C" void kernel_launch(void* const* d_in, const int* in_sizes, int n_in,
                              void* d_out, int out_size)
{
    const float* x       = (const float*)d_in[0];
    const int*   row     = (const int*)  d_in[1];
    const int*   col     = (const int*)  d_in[2];
    const float* W0      = (const float*)d_in[3];
    const float* b0      = (const float*)d_in[4];
    const float* W1      = (const float*)d_in[5];
    const float* b1      = (const float*)d_in[6];
    const float* att     = (const float*)d_in[7];
    const float* scale0  = (const float*)d_in[8];
    const float* offset0 = (const float*)d_in[9];
    const float* scale1  = (const float*)d_in[10];
    const float* offset1 = (const float*)d_in[11];
    float* out = (float*)d_out;

    const int N = in_sizes[0] / D;
    const int E = in_sizes[1];

    cudaFuncSetAttribute(gemm_kernel, cudaFuncAttributeMaxDynamicSharedMemorySize,
                         GEMM_SMEM);

    dim3 ggrid((N + 127) / 128, 2);
    gemm_kernel<<<ggrid, 256, GEMM_SMEM>>>(x, W0, b0, W1, b1, att, N);
    hist_kernel<<<(E + 255) / 256, 256>>>(row, E);
    scan_kernel<<<1, 1024>>>(N);
    scatter_kernel<<<(E + 255) / 256, 256>>>(row, col, E);
    agg_kernel<<<(N * 32 + 255) / 256, 256>>>(scale0, offset0, scale1, offset1, out, N);
}

// round 12
// speedup vs baseline: 1.7536x; 1.4591x over previous
#include <cuda_runtime.h>
#include <cuda_fp16.h>
#include <cstdint>

#define D 128
#define NMAX 100000
#define EMAX 3200000
#define FULL 0xffffffffu

// Scratch in device globals (no runtime allocation).
__device__ float  g_h0[NMAX * D];
__device__ __half g_h1h[NMAX * D];      // h1 in fp16 (agg gather payload)
__device__ float  g_aself[NMAX];
__device__ float  g_aneigh[NMAX];
__device__ int    g_deg[NMAX + 4];
__device__ int    g_off[NMAX + 1];
__device__ int    g_cur[NMAX];
__device__ int2   g_epack[EMAX];        // {col, f32 bits of a_neigh[col]}
__device__ int    g_bsum[512];
__device__ int    g_boff[512];

// ---------------------------------------------------------------------------
// Tensor-core GEMM, fp16 mma.sync m16n8k16 (fp32 accumulate).
// Grid (ceil(N/128), 2): cb=0 -> h0 (fp32) + a_self; cb=1 -> h1 (fp16) + a_neigh.
// CTA: 256 thr (8 warps: 4 along M x 2 along N), tile 128 rows x 128 cols.
// smem 69.5 KB -> 2 CTAs/SM. fp16 mantissa == tf32 mantissa (10 bits).
// ---------------------------------------------------------------------------
#define HSTRIDE 136
#define TILE_HALVES (128 * HSTRIDE)
#define GEMM_SMEM (2 * TILE_HALVES * 2 + 3 * 128 * 4)

__device__ __forceinline__ void mma_f16(float* c, const uint32_t* a,
                                        uint32_t b0, uint32_t b1)
{
    asm volatile(
        "mma.sync.aligned.m16n8k16.row.col.f32.f16.f16.f32 "
        "{%0,%1,%2,%3}, {%4,%5,%6,%7}, {%8,%9}, {%0,%1,%2,%3};"
        : "+f"(c[0]), "+f"(c[1]), "+f"(c[2]), "+f"(c[3])
        : "r"(a[0]), "r"(a[1]), "r"(a[2]), "r"(a[3]), "r"(b0), "r"(b1));
}

__global__ __launch_bounds__(256, 2) void gemm_kernel(
    const float* __restrict__ x,
    const float* __restrict__ W0, const float* __restrict__ b0,
    const float* __restrict__ W1, const float* __restrict__ b1,
    const float* __restrict__ att, int N)
{
    extern __shared__ __half smh[];
    __half* xs = smh;                     // [128][HSTRIDE]
    __half* ws = smh + TILE_HALVES;       // [128][HSTRIDE]
    float* rowsum = (float*)(smh + 2 * TILE_HALVES);  // [128]
    float* sbias  = rowsum + 128;                     // [128]
    float* satt   = sbias + 128;                      // [128]

    const int tid  = threadIdx.x;
    const int row0 = blockIdx.x * 128;
    const int cb   = blockIdx.y;
    const float* W  = cb ? W1 : W0;
    const float* bv = cb ? b1 : b0;

    if (tid < 128) {
        rowsum[tid] = 0.0f;
        sbias[tid]  = bv[tid];
        satt[tid]   = att[cb * 128 + tid];
        if (cb == 0 && row0 + tid < N) g_deg[row0 + tid] = 0;
    }

    // Stage W and x tiles as fp16: float4 loads -> 2x half2 stores.
    for (int i = tid; i < 128 * 32; i += 256) {
        int r = i >> 5, c4 = (i & 31) * 4;
        float4 wv = *(const float4*)(W + r * 128 + c4);
        *(__half2*)(ws + r * HSTRIDE + c4)     = __floats2half2_rn(wv.x, wv.y);
        *(__half2*)(ws + r * HSTRIDE + c4 + 2) = __floats2half2_rn(wv.z, wv.w);
        int gr = row0 + r;
        float4 xv = (gr < N) ? *(const float4*)(x + (size_t)gr * 128 + c4)
                             : make_float4(0.f, 0.f, 0.f, 0.f);
        *(__half2*)(xs + r * HSTRIDE + c4)     = __floats2half2_rn(xv.x, xv.y);
        *(__half2*)(xs + r * HSTRIDE + c4 + 2) = __floats2half2_rn(xv.z, xv.w);
    }
    __syncthreads();

    const int lane = tid & 31, wid = tid >> 5;
    const int gid  = lane >> 2, tg = lane & 3;
    const int mrow = (wid >> 1) * 32;   // 0,32,64,96
    const int ncol = (wid & 1) * 64;    // 0,64

    float acc[2][8][4];
#pragma unroll
    for (int mt = 0; mt < 2; mt++)
#pragma unroll
        for (int nt = 0; nt < 8; nt++)
#pragma unroll
            for (int q = 0; q < 4; q++) acc[mt][nt][q] = 0.0f;

#pragma unroll
    for (int ks = 0; ks < 8; ks++) {
        const int k0 = ks * 16;
        uint32_t a[2][4];
#pragma unroll
        for (int mt = 0; mt < 2; mt++) {
            int r = mrow + mt * 16 + gid;
            a[mt][0] = *(const uint32_t*)(xs + (r    ) * HSTRIDE + k0     + tg * 2);
            a[mt][1] = *(const uint32_t*)(xs + (r + 8) * HSTRIDE + k0     + tg * 2);
            a[mt][2] = *(const uint32_t*)(xs + (r    ) * HSTRIDE + k0 + 8 + tg * 2);
            a[mt][3] = *(const uint32_t*)(xs + (r + 8) * HSTRIDE + k0 + 8 + tg * 2);
        }
#pragma unroll
        for (int nt = 0; nt < 8; nt++) {
            int n = ncol + nt * 8 + gid;
            uint32_t bq0 = *(const uint32_t*)(ws + n * HSTRIDE + k0     + tg * 2);
            uint32_t bq1 = *(const uint32_t*)(ws + n * HSTRIDE + k0 + 8 + tg * 2);
#pragma unroll
            for (int mt = 0; mt < 2; mt++)
                mma_f16(acc[mt][nt], a[mt], bq0, bq1);
        }
    }

    // Epilogue: bias + relu, store h (fp32 h0 / fp16 h1), attention dot per row.
    float pr[2][2] = {{0.f, 0.f}, {0.f, 0.f}};
#pragma unroll
    for (int mt = 0; mt < 2; mt++) {
        int rbase = row0 + mrow + mt * 16;
#pragma unroll
        for (int nt = 0; nt < 8; nt++) {
            int n = ncol + nt * 8 + 2 * tg;
            float bia0 = sbias[n], bia1 = sbias[n + 1];
            float at0  = satt[n],  at1  = satt[n + 1];
            float v00 = fmaxf(acc[mt][nt][0] + bia0, 0.0f);
            float v01 = fmaxf(acc[mt][nt][1] + bia1, 0.0f);
            float v10 = fmaxf(acc[mt][nt][2] + bia0, 0.0f);
            float v11 = fmaxf(acc[mt][nt][3] + bia1, 0.0f);
            int r0r = rbase + gid, r1r = rbase + gid + 8;
            if (cb == 0) {
                if (r0r < N) *(float2*)(g_h0 + (size_t)r0r * 128 + n) = make_float2(v00, v01);
                if (r1r < N) *(float2*)(g_h0 + (size_t)r1r * 128 + n) = make_float2(v10, v11);
            } else {
                if (r0r < N) *(__half2*)(g_h1h + (size_t)r0r * 128 + n) =
                    __floats2half2_rn(v00, v01);
                if (r1r < N) *(__half2*)(g_h1h + (size_t)r1r * 128 + n) =
                    __floats2half2_rn(v10, v11);
            }
            pr[mt][0] += v00 * at0 + v01 * at1;
            pr[mt][1] += v10 * at0 + v11 * at1;
        }
    }
#pragma unroll
    for (int mt = 0; mt < 2; mt++)
#pragma unroll
        for (int h = 0; h < 2; h++) {
            float p = pr[mt][h];
            p += __shfl_xor_sync(FULL, p, 1);
            p += __shfl_xor_sync(FULL, p, 2);
            pr[mt][h] = p;
        }
    if (tg == 0) {
        atomicAdd(&rowsum[mrow + gid     ], pr[0][0]);
        atomicAdd(&rowsum[mrow + gid + 8 ], pr[0][1]);
        atomicAdd(&rowsum[mrow + gid + 16], pr[1][0]);
        atomicAdd(&rowsum[mrow + gid + 24], pr[1][1]);
    }
    __syncthreads();
    if (tid < 128) {
        int gr = row0 + tid;
        if (gr < N) {
            float p = rowsum[tid];
            p = (p > 0.0f) ? p : 0.2f * p;
            if (cb) g_aneigh[gr] = p;
            else    g_aself[gr]  = p;
        }
    }
}

// ---------------------------------------------------------------------------
// CSR build: histogram (x4 unrolled) -> 3-kernel scan -> scatter (x4 unrolled)
// ---------------------------------------------------------------------------
__global__ __launch_bounds__(256) void hist_kernel(const int* __restrict__ row, int E)
{
    int i0 = (blockIdx.x * 256 + threadIdx.x) * 4;
    if (i0 + 3 < E) {
        int4 r4 = *(const int4*)(row + i0);
        atomicAdd(&g_deg[r4.x], 1);
        atomicAdd(&g_deg[r4.y], 1);
        atomicAdd(&g_deg[r4.z], 1);
        atomicAdd(&g_deg[r4.w], 1);
    } else {
        for (int i = i0; i < E; i++) atomicAdd(&g_deg[row[i]], 1);
    }
}

__global__ __launch_bounds__(512) void scan1_kernel(int N)
{
    int t = threadIdx.x, b = blockIdx.x;
    int i = b * 512 + t;
    int lane = t & 31, w = t >> 5;
    int v = (i < N) ? g_deg[i] : 0;
#pragma unroll
    for (int o = 1; o < 32; o <<= 1) {
        int n = __shfl_up_sync(FULL, v, o);
        if (lane >= o) v += n;
    }
    __shared__ int ws[16];
    if (lane == 31) ws[w] = v;
    __syncthreads();
    if (w == 0) {
        int s = (lane < 16) ? ws[lane] : 0;
#pragma unroll
        for (int o = 1; o < 16; o <<= 1) {
            int n = __shfl_up_sync(FULL, s, o);
            if (lane >= o) s += n;
        }
        if (lane < 16) ws[lane] = s;
    }
    __syncthreads();
    if (w > 0) v += ws[w - 1];
    if (i < N) g_off[i + 1] = v;
    if (t == 511) g_bsum[b] = v;
}

__global__ __launch_bounds__(512) void scan2_kernel(int nb)
{
    int t = threadIdx.x;
    int lane = t & 31, w = t >> 5;
    int orig = (t < nb) ? g_bsum[t] : 0;
    int v = orig;
#pragma unroll
    for (int o = 1; o < 32; o <<= 1) {
        int n = __shfl_up_sync(FULL, v, o);
        if (lane >= o) v += n;
    }
    __shared__ int ws[16];
    if (lane == 31) ws[w] = v;
    __syncthreads();
    if (w == 0) {
        int s = (lane < 16) ? ws[lane] : 0;
#pragma unroll
        for (int o = 1; o < 16; o <<= 1) {
            int n = __shfl_up_sync(FULL, s, o);
            if (lane >= o) s += n;
        }
        if (lane < 16) ws[lane] = s;
    }
    __syncthreads();
    if (w > 0) v += ws[w - 1];
    if (t < nb) g_boff[t] = v - orig;   // exclusive
}

__global__ __launch_bounds__(512) void scan3_kernel(int N)
{
    int t = threadIdx.x, b = blockIdx.x;
    int i = b * 512 + t;
    if (i < N) {
        int val = g_off[i + 1] + g_boff[b];
        g_off[i + 1] = val;
        g_cur[i] = val - g_deg[i];
    }
    if (i == 0) g_off[0] = 0;
}

__global__ __launch_bounds__(256) void scatter_kernel(
    const int* __restrict__ row, const int* __restrict__ col, int E)
{
    int i0 = (blockIdx.x * 256 + threadIdx.x) * 4;
    if (i0 + 3 < E) {
        int4 r4 = *(const int4*)(row + i0);
        int4 c4 = *(const int4*)(col + i0);
        float a0 = g_aneigh[c4.x], a1 = g_aneigh[c4.y];
        float a2 = g_aneigh[c4.z], a3 = g_aneigh[c4.w];
        int p0 = atomicAdd(&g_cur[r4.x], 1);
        int p1 = atomicAdd(&g_cur[r4.y], 1);
        int p2 = atomicAdd(&g_cur[r4.z], 1);
        int p3 = atomicAdd(&g_cur[r4.w], 1);
        g_epack[p0] = make_int2(c4.x, __float_as_int(a0));
        g_epack[p1] = make_int2(c4.y, __float_as_int(a1));
        g_epack[p2] = make_int2(c4.z, __float_as_int(a2));
        g_epack[p3] = make_int2(c4.w, __float_as_int(a3));
    } else {
        for (int i = i0; i < E; i++) {
            int c = col[i];
            int pos = atomicAdd(&g_cur[row[i]], 1);
            g_epack[pos] = make_int2(c, __float_as_int(g_aneigh[c]));
        }
    }
}

// ---------------------------------------------------------------------------
// Aggregate + fused epilogue: one warp per node (gather, no atomics).
//   agg = sum_{(r,c)} (a_self[r]+a_neigh[c]) * h1[c]   (h1 fp16, e pre-packed)
//   out[r] = norm(h0[r],s0,o0) + norm(agg,s1,o1)
// ---------------------------------------------------------------------------
__global__ __launch_bounds__(256) void agg_kernel(
    const float* __restrict__ scale0, const float* __restrict__ offset0,
    const float* __restrict__ scale1, const float* __restrict__ offset1,
    float* __restrict__ out, int N)
{
    int gw = (blockIdx.x * blockDim.x + threadIdx.x) >> 5;
    int lane = threadIdx.x & 31;
    if (gw >= N) return;

    const int start = g_off[gw];
    const int end   = g_off[gw + 1];
    const float a_r = g_aself[gw];

    float4 acc = make_float4(0.f, 0.f, 0.f, 0.f);

    for (int base = start; base < end; base += 32) {
        int idx = base + lane;
        int2 p = (idx < end) ? g_epack[idx] : make_int2(0, 0);
        int   c = p.x;
        float e = a_r + __int_as_float(p.y);
        int cnt = min(32, end - base);
        int j = 0;
        for (; j + 4 <= cnt; j += 4) {
#pragma unroll
            for (int u = 0; u < 4; u++) {
                int   cj = __shfl_sync(FULL, c, j + u);
                float ej = __shfl_sync(FULL, e, j + u);
                uint2 hp = ((const uint2*)(g_h1h + (size_t)cj * 128))[lane];
                float2 lo = __half22float2(*(__half2*)&hp.x);
                float2 hi = __half22float2(*(__half2*)&hp.y);
                acc.x = fmaf(ej, lo.x, acc.x);
                acc.y = fmaf(ej, lo.y, acc.y);
                acc.z = fmaf(ej, hi.x, acc.z);
                acc.w = fmaf(ej, hi.y, acc.w);
            }
        }
        for (; j < cnt; j++) {
            int   cj = __shfl_sync(FULL, c, j);
            float ej = __shfl_sync(FULL, e, j);
            uint2 hp = ((const uint2*)(g_h1h + (size_t)cj * 128))[lane];
            float2 lo = __half22float2(*(__half2*)&hp.x);
            float2 hi = __half22float2(*(__half2*)&hp.y);
            acc.x = fmaf(ej, lo.x, acc.x);
            acc.y = fmaf(ej, lo.y, acc.y);
            acc.z = fmaf(ej, hi.x, acc.z);
            acc.w = fmaf(ej, hi.y, acc.w);
        }
    }

    const float4 h0v = ((const float4*)(g_h0 + (size_t)gw * 128))[lane];

    float s0 = h0v.x + h0v.y + h0v.z + h0v.w;
    float q0 = h0v.x * h0v.x + h0v.y * h0v.y + h0v.z * h0v.z + h0v.w * h0v.w;
    float s1 = acc.x + acc.y + acc.z + acc.w;
    float q1 = acc.x * acc.x + acc.y * acc.y + acc.z * acc.z + acc.w * acc.w;

#pragma unroll
    for (int o = 16; o > 0; o >>= 1) {
        s0 += __shfl_xor_sync(FULL, s0, o);
        q0 += __shfl_xor_sync(FULL, q0, o);
        s1 += __shfl_xor_sync(FULL, s1, o);
        q1 += __shfl_xor_sync(FULL, q1, o);
    }

    const float m0 = s0 * (1.0f / 128.0f);
    const float i0 = rsqrtf(q0 * (1.0f / 128.0f) - m0 * m0 + 1e-9f);
    const float m1 = s1 * (1.0f / 128.0f);
    const float i1 = rsqrtf(q1 * (1.0f / 128.0f) - m1 * m1 + 1e-9f);

    const float4 sc0 = ((const float4*)scale0)[lane];
    const float4 of0 = ((const float4*)offset0)[lane];
    const float4 sc1 = ((const float4*)scale1)[lane];
    const float4 of1 = ((const float4*)offset1)[lane];

    float4 o4;
    o4.x = (h0v.x - m0) * sc0.x * i0 + of0.x + (acc.x - m1) * sc1.x * i1 + of1.x;
    o4.y = (h0v.y - m0) * sc0.y * i0 + of0.y + (acc.y - m1) * sc1.y * i1 + of1.y;
    o4.z = (h0v.z - m0) * sc0.z * i0 + of0.z + (acc.z - m1) * sc1.z * i1 + of1.z;
    o4.w = (h0v.w - m0) * sc0.w * i0 + of0.w + (acc.w - m1) * sc1.w * i1 + of1.w;
    ((float4*)(out + (size_t)gw * 128))[lane] = o4;
}

// ---------------------------------------------------------------------------
extern "C" void kernel_launch(void* const* d_in, const int* in_sizes, int n_in,
                              void* d_out, int out_size)
{
    const float* x       = (const float*)d_in[0];
    const int*   row     = (const int*)  d_in[1];
    const int*   col     = (const int*)  d_in[2];
    const float* W0      = (const float*)d_in[3];
    const float* b0      = (const float*)d_in[4];
    const float* W1      = (const float*)d_in[5];
    const float* b1      = (const float*)d_in[6];
    const float* att     = (const float*)d_in[7];
    const float* scale0  = (const float*)d_in[8];
    const float* offset0 = (const float*)d_in[9];
    const float* scale1  = (const float*)d_in[10];
    const float* offset1 = (const float*)d_in[11];
    float* out = (float*)d_out;

    const int N = in_sizes[0] / D;
    const int E = in_sizes[1];
    const int nb = (N + 511) / 512;

    cudaFuncSetAttribute(gemm_kernel, cudaFuncAttributeMaxDynamicSharedMemorySize,
                         GEMM_SMEM);

    dim3 ggrid((N + 127) / 128, 2);
    gemm_kernel<<<ggrid, 256, GEMM_SMEM>>>(x, W0, b0, W1, b1, att, N);
    hist_kernel<<<(E / 4 + 255) / 256, 256>>>(row, E);
    scan1_kernel<<<nb, 512>>>(N);
    scan2_kernel<<<1, 512>>>(nb);
    scan3_kernel<<<nb, 512>>>(N);
    scatter_kernel<<<(E / 4 + 255) / 256, 256>>>(row, col, E);
    agg_kernel<<<(N * 32 + 255) / 256, 256>>>(scale0, offset0, scale1, offset1, out, N);
}